// round 4
// baseline (speedup 1.0000x reference)
#include <cuda_runtime.h>
#include <math.h>

#define S_LEN 2048
#define HID   2048
#define NHEAD 16
#define HD    128

#define ATT_SCALE 0.08838834764831843f   // 128^-0.5

// Scratch (device globals — no allocation allowed)
__device__ float g_q[NHEAD * S_LEN * HD];
__device__ float g_k[NHEAD * S_LEN * HD];
__device__ float g_v[NHEAD * S_LEN * HD];
__device__ float g_attn[NHEAD * S_LEN * HD];
__device__ float g_oM[NHEAD * S_LEN * HD];   // masked-block normalized output snapshot

// ---------------------------------------------------------------------------
// QKV projection: Y = X @ W^T + b, written directly in (head, s, d) layout.
// ---------------------------------------------------------------------------
__global__ __launch_bounds__(256) void qkv_gemm_kernel(
    const float* __restrict__ X,
    const float* __restrict__ qw, const float* __restrict__ qb,
    const float* __restrict__ kw, const float* __restrict__ kb,
    const float* __restrict__ vw, const float* __restrict__ vb)
{
    __shared__ float As[16][132];
    __shared__ float Bs[16][132];

    const int z = blockIdx.z;
    const float* __restrict__ W    = (z == 0) ? qw : (z == 1) ? kw : vw;
    const float* __restrict__ bias = (z == 0) ? qb : (z == 1) ? kb : vb;
    float* dst = (z == 0) ? g_q : (z == 1) ? g_k : g_v;

    const int mbase = blockIdx.x * 128;
    const int head  = blockIdx.y;
    const int nbase = head * 128;
    const int tid = threadIdx.x;
    const int ty = tid >> 4;
    const int tx = tid & 15;

    float acc[8][8];
#pragma unroll
    for (int r = 0; r < 8; r++)
#pragma unroll
        for (int c = 0; c < 8; c++) acc[r][c] = 0.f;

    for (int kt = 0; kt < HID; kt += 16) {
        __syncthreads();
#pragma unroll
        for (int i = tid; i < 2048; i += 256) {
            int r = i >> 4, kk = i & 15;
            As[kk][r] = X[(size_t)(mbase + r) * HID + kt + kk];
            Bs[kk][r] = W[(size_t)(nbase + r) * HID + kt + kk];
        }
        __syncthreads();
#pragma unroll
        for (int kk = 0; kk < 16; kk++) {
            float a[8], b[8];
            *(float4*)&a[0] = *(const float4*)&As[kk][ty * 8];
            *(float4*)&a[4] = *(const float4*)&As[kk][ty * 8 + 4];
            *(float4*)&b[0] = *(const float4*)&Bs[kk][tx * 8];
            *(float4*)&b[4] = *(const float4*)&Bs[kk][tx * 8 + 4];
#pragma unroll
            for (int r = 0; r < 8; r++)
#pragma unroll
                for (int c = 0; c < 8; c++)
                    acc[r][c] += a[r] * b[c];
        }
    }

    float bv[8];
#pragma unroll
    for (int c = 0; c < 8; c++) bv[c] = bias[nbase + tx * 8 + c];

    float* dbase = dst + (size_t)head * S_LEN * HD;
#pragma unroll
    for (int r = 0; r < 8; r++) {
        int row = mbase + ty * 8 + r;
        float4 v0, v1;
        v0.x = acc[r][0] + bv[0]; v0.y = acc[r][1] + bv[1];
        v0.z = acc[r][2] + bv[2]; v0.w = acc[r][3] + bv[3];
        v1.x = acc[r][4] + bv[4]; v1.y = acc[r][5] + bv[5];
        v1.z = acc[r][6] + bv[6]; v1.w = acc[r][7] + bv[7];
        *(float4*)&dbase[(size_t)row * HD + tx * 8]     = v0;
        *(float4*)&dbase[(size_t)row * HD + tx * 8 + 4] = v1;
    }
}

// ---------------------------------------------------------------------------
// Attention, faithful to the reference ring recurrence:
//   final = (a*o_M + 3*o_U) / (a*L_Mloc + 3*L_U + 1e-8),  a = exp(m_M - m_U)
// Single flash pass: tiles 0..qt-1 full, diag masked (snapshot M), diag
// anti-masked, tiles qt+1..15 full -> U stats at the end.
// ---------------------------------------------------------------------------
__global__ __launch_bounds__(256) void attn_kernel()
{
    extern __shared__ float sm[];
    float* Qs = sm;                        // 128 * 132
    float* Ks = sm + 128 * 132;            // 128 * 132
    float* Ps = sm + 2 * 128 * 132;        // 128 * 128
    float* Vs = Ps + 128 * 128;            // 16  * 128

    const int h = blockIdx.y;
    const int qt = blockIdx.x;
    const int qbase = qt * 128;
    const int tid = threadIdx.x;
    const int ty = tid >> 4;
    const int tx = tid & 15;

    const float* __restrict__ Qg = g_q + (size_t)h * S_LEN * HD;
    const float* __restrict__ Kg = g_k + (size_t)h * S_LEN * HD;
    const float* __restrict__ Vg = g_v + (size_t)h * S_LEN * HD;

    // Load Q tile transposed: Qs[d][q]
    for (int i = tid; i < 128 * 128; i += 256) {
        int q = i >> 7, d = i & 127;
        Qs[d * 132 + q] = Qg[(size_t)(qbase + q) * HD + d];
    }

    float m[8], l[8], o[8][8];
    float mMs[8], lMs[8];                  // masked-stats snapshot scalars
    float sacc[8][8];
#pragma unroll
    for (int r = 0; r < 8; r++) {
        m[r] = -INFINITY; l[r] = 0.f; mMs[r] = -INFINITY; lMs[r] = 0.f;
#pragma unroll
        for (int c = 0; c < 8; c++) o[r][c] = 0.f;
    }

    const int iq0 = qbase + ty * 8;
    int kt_cur = 0;

    // mode 0 = full tile, 1 = masked (j <= i), 2 = anti-masked (j > i)
    auto process_tile = [&](int mode) {
        __syncthreads();   // prior Ps readers done before we rewrite Ps
#pragma unroll
        for (int r = 0; r < 8; r++) {
            const int irow = iq0 + r;
            float t[8];
            float bm = -INFINITY;
#pragma unroll
            for (int c = 0; c < 8; c++) {
                int j = kt_cur + tx * 8 + c;
                float sv = sacc[r][c];
                if (mode == 1 && j > irow)  sv = -INFINITY;
                if (mode == 2 && j <= irow) sv = -INFINITY;
                t[c] = sv;
                bm = fmaxf(bm, sv);
            }
#pragma unroll
            for (int off = 8; off > 0; off >>= 1)
                bm = fmaxf(bm, __shfl_xor_sync(0xffffffffu, bm, off));
            float mn = fmaxf(m[r], bm);
            float f = expf(m[r] - mn);
            float rs = 0.f;
#pragma unroll
            for (int c = 0; c < 8; c++) {
                float p = expf(t[c] - mn);
                t[c] = p;
                rs += p;
            }
#pragma unroll
            for (int off = 8; off > 0; off >>= 1)
                rs += __shfl_xor_sync(0xffffffffu, rs, off);
            l[r] = l[r] * f + rs;
            m[r] = mn;
#pragma unroll
            for (int c = 0; c < 8; c++) o[r][c] *= f;
            *(float4*)&Ps[(ty * 8 + r) * 128 + tx * 8] =
                make_float4(t[0], t[1], t[2], t[3]);
            *(float4*)&Ps[(ty * 8 + r) * 128 + tx * 8 + 4] =
                make_float4(t[4], t[5], t[6], t[7]);
        }

        // O += P @ V, V streamed in 16-row chunks
        for (int kc = 0; kc < 128; kc += 16) {
            __syncthreads();   // first one fences Ps writes
            for (int i = tid; i < 16 * 128; i += 256) {
                int kk = i >> 7, d = i & 127;
                Vs[kk * 128 + d] = Vg[(size_t)(kt_cur + kc + kk) * HD + d];
            }
            __syncthreads();
#pragma unroll
            for (int kk = 0; kk < 16; kk++) {
                float a[8], b[8];
#pragma unroll
                for (int r = 0; r < 8; r++)
                    a[r] = Ps[(ty * 8 + r) * 128 + kc + kk];
                *(float4*)&b[0] = *(const float4*)&Vs[kk * 128 + tx * 8];
                *(float4*)&b[4] = *(const float4*)&Vs[kk * 128 + tx * 8 + 4];
#pragma unroll
                for (int r = 0; r < 8; r++)
#pragma unroll
                    for (int c = 0; c < 8; c++)
                        o[r][c] += a[r] * b[c];
            }
        }
    };

    for (int kt = 0; kt < S_LEN; kt += 128) {
        kt_cur = kt;
        __syncthreads();
        // Load K tile transposed: Ks[d][k]
        for (int i = tid; i < 128 * 128; i += 256) {
            int kc = i >> 7, d = i & 127;
            Ks[d * 132 + kc] = Kg[(size_t)(kt + kc) * HD + d];
        }
        __syncthreads();   // also covers initial Qs load

        // S = Q K^T (scaled)
#pragma unroll
        for (int r = 0; r < 8; r++)
#pragma unroll
            for (int c = 0; c < 8; c++) sacc[r][c] = 0.f;
#pragma unroll 8
        for (int d = 0; d < 128; d++) {
            float a[8], b[8];
            *(float4*)&a[0] = *(const float4*)&Qs[d * 132 + ty * 8];
            *(float4*)&a[4] = *(const float4*)&Qs[d * 132 + ty * 8 + 4];
            *(float4*)&b[0] = *(const float4*)&Ks[d * 132 + tx * 8];
            *(float4*)&b[4] = *(const float4*)&Ks[d * 132 + tx * 8 + 4];
#pragma unroll
            for (int r = 0; r < 8; r++)
#pragma unroll
                for (int c = 0; c < 8; c++)
                    sacc[r][c] += a[r] * b[c];
        }
#pragma unroll
        for (int r = 0; r < 8; r++)
#pragma unroll
            for (int c = 0; c < 8; c++) sacc[r][c] *= ATT_SCALE;

        if ((kt >> 7) == qt) {
            // Masked diagonal: accumulators become the M (causal) stats.
            process_tile(1);
            // Snapshot normalized masked output to global scratch.
#pragma unroll
            for (int r = 0; r < 8; r++) {
                mMs[r] = m[r];
                lMs[r] = l[r];
                float inv = 1.f / (l[r] + 1e-8f);
                size_t base = (size_t)h * S_LEN * HD +
                              (size_t)(qbase + ty * 8 + r) * HD + tx * 8;
                *(float4*)&g_oM[base] = make_float4(
                    o[r][0] * inv, o[r][1] * inv, o[r][2] * inv, o[r][3] * inv);
                *(float4*)&g_oM[base + 4] = make_float4(
                    o[r][4] * inv, o[r][5] * inv, o[r][6] * inv, o[r][7] * inv);
            }
            // Anti-masked part of the diagonal completes the U accumulation.
            process_tile(2);
        } else {
            process_tile(0);
        }
    }

    // Combine: final = (a*oM + 3*oU) / (a*lM + 3*lU + 1e-8), a = exp(mM - mU)
    float* Og = g_attn + (size_t)h * S_LEN * HD;
#pragma unroll
    for (int r = 0; r < 8; r++) {
        float a = expf(mMs[r] - m[r]);
        float invU = 1.f / (l[r] + 1e-8f);
        float invden = 1.f / (a * lMs[r] + 3.f * l[r] + 1e-8f);
        size_t base = (size_t)h * S_LEN * HD +
                      (size_t)(qbase + ty * 8 + r) * HD + tx * 8;
        float4 om0 = *(const float4*)&g_oM[base];
        float4 om1 = *(const float4*)&g_oM[base + 4];
        float4 r0, r1;
        r0.x = (a * om0.x + 3.f * o[r][0] * invU) * invden;
        r0.y = (a * om0.y + 3.f * o[r][1] * invU) * invden;
        r0.z = (a * om0.z + 3.f * o[r][2] * invU) * invden;
        r0.w = (a * om0.w + 3.f * o[r][3] * invU) * invden;
        r1.x = (a * om1.x + 3.f * o[r][4] * invU) * invden;
        r1.y = (a * om1.y + 3.f * o[r][5] * invU) * invden;
        r1.z = (a * om1.z + 3.f * o[r][6] * invU) * invden;
        r1.w = (a * om1.w + 3.f * o[r][7] * invU) * invden;
        *(float4*)&Og[base - (size_t)h * S_LEN * HD + 0] = r0;   // same offset, g_attn base
        *(float4*)&Og[base - (size_t)h * S_LEN * HD + 4] = r1;
    }
}

// ---------------------------------------------------------------------------
// Output projection: out = A @ o_w^T + o_b, A in (head, s, d) layout.
// ---------------------------------------------------------------------------
__global__ __launch_bounds__(256) void out_gemm_kernel(
    const float* __restrict__ ow, const float* __restrict__ ob,
    float* __restrict__ out)
{
    __shared__ float As[16][132];
    __shared__ float Bs[16][132];

    const int mbase = blockIdx.x * 128;
    const int nbase = blockIdx.y * 128;
    const int tid = threadIdx.x;
    const int ty = tid >> 4;
    const int tx = tid & 15;

    float acc[8][8];
#pragma unroll
    for (int r = 0; r < 8; r++)
#pragma unroll
        for (int c = 0; c < 8; c++) acc[r][c] = 0.f;

    for (int kt = 0; kt < HID; kt += 16) {
        __syncthreads();
#pragma unroll
        for (int i = tid; i < 2048; i += 256) {
            int r = i >> 4, kk = i & 15;
            int kg = kt + kk;
            As[kk][r] = g_attn[(size_t)(kg >> 7) * (S_LEN * HD) +
                               (size_t)(mbase + r) * HD + (kg & 127)];
            Bs[kk][r] = ow[(size_t)(nbase + r) * HID + kg];
        }
        __syncthreads();
#pragma unroll
        for (int kk = 0; kk < 16; kk++) {
            float a[8], b[8];
            *(float4*)&a[0] = *(const float4*)&As[kk][ty * 8];
            *(float4*)&a[4] = *(const float4*)&As[kk][ty * 8 + 4];
            *(float4*)&b[0] = *(const float4*)&Bs[kk][tx * 8];
            *(float4*)&b[4] = *(const float4*)&Bs[kk][tx * 8 + 4];
#pragma unroll
            for (int r = 0; r < 8; r++)
#pragma unroll
                for (int c = 0; c < 8; c++)
                    acc[r][c] += a[r] * b[c];
        }
    }

    float bv[8];
#pragma unroll
    for (int c = 0; c < 8; c++) bv[c] = ob[nbase + tx * 8 + c];

#pragma unroll
    for (int r = 0; r < 8; r++) {
        int row = mbase + ty * 8 + r;
        float4 v0, v1;
        v0.x = acc[r][0] + bv[0]; v0.y = acc[r][1] + bv[1];
        v0.z = acc[r][2] + bv[2]; v0.w = acc[r][3] + bv[3];
        v1.x = acc[r][4] + bv[4]; v1.y = acc[r][5] + bv[5];
        v1.z = acc[r][6] + bv[6]; v1.w = acc[r][7] + bv[7];
        *(float4*)&out[(size_t)row * HID + nbase + tx * 8]     = v0;
        *(float4*)&out[(size_t)row * HID + nbase + tx * 8 + 4] = v1;
    }
}

extern "C" void kernel_launch(void* const* d_in, const int* in_sizes, int n_in,
                              void* d_out, int out_size)
{
    const float* X  = (const float*)d_in[0];
    const float* qw = (const float*)d_in[1];
    const float* qb = (const float*)d_in[2];
    const float* kw = (const float*)d_in[3];
    const float* kb = (const float*)d_in[4];
    const float* vw = (const float*)d_in[5];
    const float* vb = (const float*)d_in[6];
    const float* ow = (const float*)d_in[7];
    const float* ob = (const float*)d_in[8];
    float* out = (float*)d_out;

    qkv_gemm_kernel<<<dim3(16, 16, 3), 256>>>(X, qw, qb, kw, kb, vw, vb);

    const int smem_bytes = (2 * 128 * 132 + 128 * 128 + 16 * 128) * (int)sizeof(float);
    cudaFuncSetAttribute(attn_kernel,
                         cudaFuncAttributeMaxDynamicSharedMemorySize, smem_bytes);
    attn_kernel<<<dim3(16, 16), 256, smem_bytes>>>();

    out_gemm_kernel<<<dim3(16, 16), 256>>>(ow, ob, out);
}

// round 6
// speedup vs baseline: 3.3039x; 3.3039x over previous
#include <cuda_runtime.h>
#include <cuda_bf16.h>
#include <math.h>

#define S_LEN 2048
#define HID   2048
#define NHEAD 16
#define HD    128

#define ATT_SCALE 0.08838834764831843f   // 128^-0.5

// Scratch (device globals — no allocation allowed)
__device__ float g_q[NHEAD * S_LEN * HD];
__device__ float g_k[NHEAD * S_LEN * HD];
__device__ float g_v[NHEAD * S_LEN * HD];
__device__ float g_attn[NHEAD * S_LEN * HD];

// ---------------------------------------------------------------------------
// MMA / ldmatrix helpers (sm_80+ mma.sync path, valid on sm_103a)
// ---------------------------------------------------------------------------
__device__ __forceinline__ void ldsm4(const void* p, unsigned* r) {
    unsigned a = (unsigned)__cvta_generic_to_shared(p);
    asm volatile("ldmatrix.sync.aligned.m8n8.x4.shared.b16 {%0,%1,%2,%3}, [%4];"
                 : "=r"(r[0]), "=r"(r[1]), "=r"(r[2]), "=r"(r[3]) : "r"(a));
}
__device__ __forceinline__ void ldsm4t(const void* p, unsigned* r) {
    unsigned a = (unsigned)__cvta_generic_to_shared(p);
    asm volatile("ldmatrix.sync.aligned.m8n8.x4.trans.shared.b16 {%0,%1,%2,%3}, [%4];"
                 : "=r"(r[0]), "=r"(r[1]), "=r"(r[2]), "=r"(r[3]) : "r"(a));
}
__device__ __forceinline__ void mma_bf(float* c, const unsigned* a, const unsigned* b) {
    asm volatile("mma.sync.aligned.m16n8k16.row.col.f32.bf16.bf16.f32 "
                 "{%0,%1,%2,%3},{%4,%5,%6,%7},{%8,%9},{%0,%1,%2,%3};"
                 : "+f"(c[0]), "+f"(c[1]), "+f"(c[2]), "+f"(c[3])
                 : "r"(a[0]), "r"(a[1]), "r"(a[2]), "r"(a[3]),
                   "r"(b[0]), "r"(b[1]));
}
__device__ __forceinline__ float bf16rt(float x) {
    return __bfloat162float(__float2bfloat16_rn(x));
}
__device__ __forceinline__ unsigned packbf(float a, float b) {
    __nv_bfloat162 t = __floats2bfloat162_rn(a, b);
    return reinterpret_cast<unsigned&>(t);
}

// ===========================================================================
// QKV projection: Y = X @ W^T + b -> (head, s, d) layout.  Split-bf16 MMA.
// Block 128x128, BK=32 fp32, 8 warps (2x4), warp tile 64x32.
// ===========================================================================
__global__ __launch_bounds__(256, 2) void qkv_gemm_kernel(
    const float* __restrict__ X,
    const float* __restrict__ qw, const float* __restrict__ qb,
    const float* __restrict__ kw, const float* __restrict__ kb,
    const float* __restrict__ vw, const float* __restrict__ vb)
{
    __shared__ __nv_bfloat16 As_hi[128][40];
    __shared__ __nv_bfloat16 As_lo[128][40];
    __shared__ __nv_bfloat16 Bs_hi[128][40];
    __shared__ __nv_bfloat16 Bs_lo[128][40];

    const int z = blockIdx.z;
    const float* __restrict__ W    = (z == 0) ? qw : (z == 1) ? kw : vw;
    const float* __restrict__ bias = (z == 0) ? qb : (z == 1) ? kb : vb;
    float* dst = (z == 0) ? g_q : (z == 1) ? g_k : g_v;

    const int mbase = blockIdx.x * 128;
    const int head  = blockIdx.y;
    const int nbase = head * 128;
    const int tid  = threadIdx.x;
    const int lane = tid & 31;
    const int warp = tid >> 5;
    const int wy = warp >> 2;       // 0..1  (m)
    const int wx = warp & 3;        // 0..3  (n)
    const int g = lane >> 2;
    const int t = lane & 3;

    const int a_row  = lane & 15;
    const int a_csel = (lane >> 4) << 3;
    const int b_row  = (lane & 7) + ((lane >> 4) & 1) * 8;
    const int b_csel = ((lane >> 3) & 1) * 8;

    float acc[4][4][4];
#pragma unroll
    for (int mt = 0; mt < 4; mt++)
#pragma unroll
        for (int nt = 0; nt < 4; nt++)
#pragma unroll
            for (int e = 0; e < 4; e++) acc[mt][nt][e] = 0.f;

    for (int kt = 0; kt < HID; kt += 32) {
        __syncthreads();
#pragma unroll
        for (int i = 0; i < 4; i++) {
            int j = tid + i * 256;           // 0..1023
            int row = j >> 3, c4 = (j & 7) << 2;
            float4 v = *(const float4*)&X[(size_t)(mbase + row) * HID + kt + c4];
            float h0 = bf16rt(v.x), h1 = bf16rt(v.y), h2 = bf16rt(v.z), h3 = bf16rt(v.w);
            *(__nv_bfloat162*)&As_hi[row][c4]     = __floats2bfloat162_rn(h0, h1);
            *(__nv_bfloat162*)&As_hi[row][c4 + 2] = __floats2bfloat162_rn(h2, h3);
            *(__nv_bfloat162*)&As_lo[row][c4]     = __floats2bfloat162_rn(v.x - h0, v.y - h1);
            *(__nv_bfloat162*)&As_lo[row][c4 + 2] = __floats2bfloat162_rn(v.z - h2, v.w - h3);

            float4 w = *(const float4*)&W[(size_t)(nbase + row) * HID + kt + c4];
            float g0 = bf16rt(w.x), g1 = bf16rt(w.y), g2 = bf16rt(w.z), g3 = bf16rt(w.w);
            *(__nv_bfloat162*)&Bs_hi[row][c4]     = __floats2bfloat162_rn(g0, g1);
            *(__nv_bfloat162*)&Bs_hi[row][c4 + 2] = __floats2bfloat162_rn(g2, g3);
            *(__nv_bfloat162*)&Bs_lo[row][c4]     = __floats2bfloat162_rn(w.x - g0, w.y - g1);
            *(__nv_bfloat162*)&Bs_lo[row][c4 + 2] = __floats2bfloat162_rn(w.z - g2, w.w - g3);
        }
        __syncthreads();

#pragma unroll
        for (int c3 = 0; c3 < 3; c3++) {     // (Ah,Bh),(Ah,Bl),(Al,Bh)
            const __nv_bfloat16 (*Asrc)[40] = (c3 == 2) ? As_lo : As_hi;
            const __nv_bfloat16 (*Bsrc)[40] = (c3 == 1) ? Bs_lo : Bs_hi;
#pragma unroll
            for (int k16 = 0; k16 < 2; k16++) {
                int k0 = k16 * 16;
                unsigned a[4][4];
#pragma unroll
                for (int mt = 0; mt < 4; mt++)
                    ldsm4(&Asrc[wy * 64 + mt * 16 + a_row][k0 + a_csel], a[mt]);
#pragma unroll
                for (int ntp = 0; ntp < 2; ntp++) {
                    unsigned bb[4];
                    ldsm4(&Bsrc[wx * 32 + ntp * 16 + b_row][k0 + b_csel], bb);
#pragma unroll
                    for (int mt = 0; mt < 4; mt++) {
                        mma_bf(acc[mt][2 * ntp],     a[mt], bb);
                        mma_bf(acc[mt][2 * ntp + 1], a[mt], bb + 2);
                    }
                }
            }
        }
    }

    float* dbase = dst + (size_t)head * S_LEN * HD;
#pragma unroll
    for (int mt = 0; mt < 4; mt++) {
#pragma unroll
        for (int nt = 0; nt < 4; nt++) {
            int row = mbase + wy * 64 + mt * 16 + g;
            int col = wx * 32 + nt * 8 + 2 * t;
            float b0 = bias[nbase + col], b1 = bias[nbase + col + 1];
            float2 v0 = make_float2(acc[mt][nt][0] + b0, acc[mt][nt][1] + b1);
            float2 v1 = make_float2(acc[mt][nt][2] + b0, acc[mt][nt][3] + b1);
            *(float2*)&dbase[(size_t)row * HD + col]       = v0;
            *(float2*)&dbase[(size_t)(row + 8) * HD + col] = v1;
        }
    }
}

// ===========================================================================
// Attention with split-bf16 MMA. Per (head, 128-q-tile) block, 8 warps,
// each warp owns 16 q-rows x full 128 kv cols (16 n-tiles).
// Ring-faithful: tiles 0..qt-1 full, diag masked (snapshot M to smem),
// diag anti-masked, tiles qt+1..15 full -> U stats.
// ===========================================================================
template<int MODE>   // 0 full, 1 keep j<=i, 2 keep j>i
__device__ __forceinline__ void softmax_update(
    float (&s)[16][4], float (&o)[16][4], float* m, float* l,
    int row0g, int kt, int lane)
{
    const int t = lane & 3;
    float bm0 = -INFINITY, bm1 = -INFINITY;
#pragma unroll
    for (int nt = 0; nt < 16; nt++) {
#pragma unroll
        for (int e = 0; e < 2; e++) {
            int j = kt + nt * 8 + 2 * t + e;
            float v0 = s[nt][e], v1 = s[nt][2 + e];
            if (MODE == 1) { if (j > row0g)      v0 = -INFINITY;
                             if (j > row0g + 8)  v1 = -INFINITY; }
            if (MODE == 2) { if (j <= row0g)     v0 = -INFINITY;
                             if (j <= row0g + 8) v1 = -INFINITY; }
            s[nt][e] = v0; s[nt][2 + e] = v1;
            bm0 = fmaxf(bm0, v0); bm1 = fmaxf(bm1, v1);
        }
    }
    bm0 = fmaxf(bm0, __shfl_xor_sync(0xffffffffu, bm0, 1));
    bm0 = fmaxf(bm0, __shfl_xor_sync(0xffffffffu, bm0, 2));
    bm1 = fmaxf(bm1, __shfl_xor_sync(0xffffffffu, bm1, 1));
    bm1 = fmaxf(bm1, __shfl_xor_sync(0xffffffffu, bm1, 2));
    float mn0 = fmaxf(m[0], bm0), mn1 = fmaxf(m[1], bm1);
    float f0 = __expf(m[0] - mn0), f1 = __expf(m[1] - mn1);
    float rs0 = 0.f, rs1 = 0.f;
#pragma unroll
    for (int nt = 0; nt < 16; nt++) {
#pragma unroll
        for (int e = 0; e < 2; e++) {
            float p0 = __expf(s[nt][e]     - mn0);
            float p1 = __expf(s[nt][2 + e] - mn1);
            s[nt][e] = p0; s[nt][2 + e] = p1;
            rs0 += p0; rs1 += p1;
        }
    }
    rs0 += __shfl_xor_sync(0xffffffffu, rs0, 1);
    rs0 += __shfl_xor_sync(0xffffffffu, rs0, 2);
    rs1 += __shfl_xor_sync(0xffffffffu, rs1, 1);
    rs1 += __shfl_xor_sync(0xffffffffu, rs1, 2);
    l[0] = l[0] * f0 + rs0; m[0] = mn0;
    l[1] = l[1] * f1 + rs1; m[1] = mn1;
#pragma unroll
    for (int nt = 0; nt < 16; nt++) {
        o[nt][0] *= f0; o[nt][1] *= f0;
        o[nt][2] *= f1; o[nt][3] *= f1;
    }
}

#define Q_HI_OFF 0
#define Q_LO_OFF 34816
#define KV_HI_OFF 69632
#define KV_LO_OFF 104448
#define PS_OFF    139264
#define ATT_SMEM  (139264 + 128 * 132 * 4)   // 206848

__global__ __launch_bounds__(256, 1) void attn_kernel()
{
    extern __shared__ char sm[];
    __nv_bfloat16 (*Qh)[136]  = (__nv_bfloat16(*)[136])(sm + Q_HI_OFF);
    __nv_bfloat16 (*Ql)[136]  = (__nv_bfloat16(*)[136])(sm + Q_LO_OFF);
    __nv_bfloat16 (*KVh)[136] = (__nv_bfloat16(*)[136])(sm + KV_HI_OFF);
    __nv_bfloat16 (*KVl)[136] = (__nv_bfloat16(*)[136])(sm + KV_LO_OFF);
    float* Ps = (float*)(sm + PS_OFF);       // raw S scratch, then oM snapshot

    const int h  = blockIdx.y;
    const int qt = blockIdx.x;
    const int qbase = qt * 128;
    const int tid  = threadIdx.x;
    const int lane = tid & 31;
    const int warp = tid >> 5;
    const int m0 = warp * 16;
    const int g = lane >> 2;
    const int t = lane & 3;

    const float* __restrict__ Qg = g_q + (size_t)h * S_LEN * HD;
    const float* __restrict__ Kg = g_k + (size_t)h * S_LEN * HD;
    const float* __restrict__ Vg = g_v + (size_t)h * S_LEN * HD;

    // ldmatrix lane address components
    const int a_row  = lane & 15;
    const int a_csel = (lane >> 4) << 3;
    const int b_row  = (lane & 7) + ((lane >> 3) & 1) * 8;
    const int b_csel = ((lane >> 4) & 1) * 8;     // K frags: col select is lane>>4
    const int k_row  = (lane & 7) + ((lane >> 4) & 1) * 8;
    const int k_csel = ((lane >> 3) & 1) * 8;

    // Load Q tile (scaled) split into smem
#pragma unroll
    for (int i = 0; i < 16; i++) {
        int j = tid + i * 256;               // 0..4095 float4 slots
        int row = j >> 5, c4 = (j & 31) << 2;
        float4 v = *(const float4*)&Qg[(size_t)(qbase + row) * HD + c4];
        v.x *= ATT_SCALE; v.y *= ATT_SCALE; v.z *= ATT_SCALE; v.w *= ATT_SCALE;
        float h0 = bf16rt(v.x), h1 = bf16rt(v.y), h2 = bf16rt(v.z), h3 = bf16rt(v.w);
        *(__nv_bfloat162*)&Qh[row][c4]     = __floats2bfloat162_rn(h0, h1);
        *(__nv_bfloat162*)&Qh[row][c4 + 2] = __floats2bfloat162_rn(h2, h3);
        *(__nv_bfloat162*)&Ql[row][c4]     = __floats2bfloat162_rn(v.x - h0, v.y - h1);
        *(__nv_bfloat162*)&Ql[row][c4 + 2] = __floats2bfloat162_rn(v.z - h2, v.w - h3);
    }

    float sacc[16][4], oacc[16][4];
    float m[2] = {-INFINITY, -INFINITY}, l[2] = {0.f, 0.f};
    float mM[2], lM[2];
#pragma unroll
    for (int nt = 0; nt < 16; nt++)
#pragma unroll
        for (int e = 0; e < 4; e++) oacc[nt][e] = 0.f;

    const int row0g = qbase + m0 + g;        // lane's first global q row

    auto fill_kv = [&](const float* __restrict__ src, int kt) {
#pragma unroll
        for (int i = 0; i < 16; i++) {
            int j = tid + i * 256;
            int row = j >> 5, c4 = (j & 31) << 2;
            float4 v = *(const float4*)&src[(size_t)(kt + row) * HD + c4];
            float h0 = bf16rt(v.x), h1 = bf16rt(v.y), h2 = bf16rt(v.z), h3 = bf16rt(v.w);
            *(__nv_bfloat162*)&KVh[row][c4]     = __floats2bfloat162_rn(h0, h1);
            *(__nv_bfloat162*)&KVh[row][c4 + 2] = __floats2bfloat162_rn(h2, h3);
            *(__nv_bfloat162*)&KVl[row][c4]     = __floats2bfloat162_rn(v.x - h0, v.y - h1);
            *(__nv_bfloat162*)&KVl[row][c4 + 2] = __floats2bfloat162_rn(v.z - h2, v.w - h3);
        }
    };

    auto pv_accum = [&]() {
#pragma unroll
        for (int kc = 0; kc < 8; kc++) {
            // repack P fragments (hi + residual lo) from sacc n-tiles 2kc, 2kc+1
            unsigned ph[4], pl[4];
            float* s0 = sacc[2 * kc];
            float* s1 = sacc[2 * kc + 1];
            float h00 = bf16rt(s0[0]), h01 = bf16rt(s0[1]);
            float h02 = bf16rt(s0[2]), h03 = bf16rt(s0[3]);
            float h10 = bf16rt(s1[0]), h11 = bf16rt(s1[1]);
            float h12 = bf16rt(s1[2]), h13 = bf16rt(s1[3]);
            ph[0] = packbf(h00, h01); ph[1] = packbf(h02, h03);
            ph[2] = packbf(h10, h11); ph[3] = packbf(h12, h13);
            pl[0] = packbf(s0[0] - h00, s0[1] - h01);
            pl[1] = packbf(s0[2] - h02, s0[3] - h03);
            pl[2] = packbf(s1[0] - h10, s1[1] - h11);
            pl[3] = packbf(s1[2] - h12, s1[3] - h13);
#pragma unroll
            for (int dp = 0; dp < 8; dp++) {
                int d0 = dp * 16;
                unsigned vh[4], vl[4];
                ldsm4t(&KVh[kc * 16 + b_row][d0 + b_csel], vh);
                ldsm4t(&KVl[kc * 16 + b_row][d0 + b_csel], vl);
                mma_bf(oacc[2 * dp],     ph, vh);
                mma_bf(oacc[2 * dp],     ph, vl);
                mma_bf(oacc[2 * dp],     pl, vh);
                mma_bf(oacc[2 * dp + 1], ph, vh + 2);
                mma_bf(oacc[2 * dp + 1], ph, vl + 2);
                mma_bf(oacc[2 * dp + 1], pl, vh + 2);
            }
        }
    };

    for (int kt = 0; kt < S_LEN; kt += 128) {
        __syncthreads();                      // protect KV from previous PV reads
        fill_kv(Kg, kt);
        __syncthreads();

        // S = (Q*scale) @ K^T
#pragma unroll
        for (int nt = 0; nt < 16; nt++)
#pragma unroll
            for (int e = 0; e < 4; e++) sacc[nt][e] = 0.f;
#pragma unroll
        for (int kc = 0; kc < 8; kc++) {
            int k0 = kc * 16;
            unsigned qh[4], ql[4];
            ldsm4(&Qh[m0 + a_row][k0 + a_csel], qh);
            ldsm4(&Ql[m0 + a_row][k0 + a_csel], ql);
#pragma unroll
            for (int ntp = 0; ntp < 8; ntp++) {
                unsigned kh[4], kl[4];
                ldsm4(&KVh[ntp * 16 + k_row][k0 + k_csel], kh);
                ldsm4(&KVl[ntp * 16 + k_row][k0 + k_csel], kl);
                mma_bf(sacc[2 * ntp],     qh, kh);
                mma_bf(sacc[2 * ntp],     qh, kl);
                mma_bf(sacc[2 * ntp],     ql, kh);
                mma_bf(sacc[2 * ntp + 1], qh, kh + 2);
                mma_bf(sacc[2 * ntp + 1], qh, kl + 2);
                mma_bf(sacc[2 * ntp + 1], ql, kh + 2);
            }
        }

        const bool diag = ((kt >> 7) == qt);
        if (diag) {
            // stash raw scaled S (this lane's own slots)
#pragma unroll
            for (int nt = 0; nt < 16; nt++) {
                int c = nt * 8 + 2 * t;
                *(float2*)&Ps[(m0 + g) * 132 + c]     = make_float2(sacc[nt][0], sacc[nt][1]);
                *(float2*)&Ps[(m0 + 8 + g) * 132 + c] = make_float2(sacc[nt][2], sacc[nt][3]);
            }
        }

        __syncthreads();                      // all warps done reading K
        fill_kv(Vg, kt);                      // V overwrites K buffers
        __syncthreads();

        if (!diag) {
            softmax_update<0>(sacc, oacc, m, l, row0g, kt, lane);
            pv_accum();
        } else {
            softmax_update<1>(sacc, oacc, m, l, row0g, kt, lane);
            pv_accum();
            mM[0] = m[0]; lM[0] = l[0]; mM[1] = m[1]; lM[1] = l[1];
            // reload raw S, then overwrite Ps with normalized masked output oM
            float inv0 = 1.f / (l[0] + 1e-8f), inv1 = 1.f / (l[1] + 1e-8f);
#pragma unroll
            for (int nt = 0; nt < 16; nt++) {
                int c = nt * 8 + 2 * t;
                float2 r0 = *(float2*)&Ps[(m0 + g) * 132 + c];
                float2 r1 = *(float2*)&Ps[(m0 + 8 + g) * 132 + c];
                *(float2*)&Ps[(m0 + g) * 132 + c] =
                    make_float2(oacc[nt][0] * inv0, oacc[nt][1] * inv0);
                *(float2*)&Ps[(m0 + 8 + g) * 132 + c] =
                    make_float2(oacc[nt][2] * inv1, oacc[nt][3] * inv1);
                sacc[nt][0] = r0.x; sacc[nt][1] = r0.y;
                sacc[nt][2] = r1.x; sacc[nt][3] = r1.y;
            }
            softmax_update<2>(sacc, oacc, m, l, row0g, kt, lane);
            pv_accum();
        }
    }

    // Combine: final = (a*oM + 3*oU_norm) / (a*lM + 3*lU + 1e-8)
    float a0 = __expf(mM[0] - m[0]), a1 = __expf(mM[1] - m[1]);
    float invU0 = 1.f / (l[0] + 1e-8f), invU1 = 1.f / (l[1] + 1e-8f);
    float den0 = 1.f / (a0 * lM[0] + 3.f * l[0] + 1e-8f);
    float den1 = 1.f / (a1 * lM[1] + 3.f * l[1] + 1e-8f);
    float* Og = g_attn + (size_t)h * S_LEN * HD;
#pragma unroll
    for (int nt = 0; nt < 16; nt++) {
        int c = nt * 8 + 2 * t;
        float2 om0 = *(float2*)&Ps[(m0 + g) * 132 + c];
        float2 om1 = *(float2*)&Ps[(m0 + 8 + g) * 132 + c];
        float2 r0, r1;
        r0.x = (a0 * om0.x + 3.f * oacc[nt][0] * invU0) * den0;
        r0.y = (a0 * om0.y + 3.f * oacc[nt][1] * invU0) * den0;
        r1.x = (a1 * om1.x + 3.f * oacc[nt][2] * invU1) * den1;
        r1.y = (a1 * om1.y + 3.f * oacc[nt][3] * invU1) * den1;
        *(float2*)&Og[(size_t)(qbase + m0 + g) * HD + c]     = r0;
        *(float2*)&Og[(size_t)(qbase + m0 + 8 + g) * HD + c] = r1;
    }
}

// ===========================================================================
// Output projection: out = A @ o_w^T + o_b;  A read from (head, s, d) layout.
// ===========================================================================
__global__ __launch_bounds__(256, 2) void out_gemm_kernel(
    const float* __restrict__ ow, const float* __restrict__ ob,
    float* __restrict__ out)
{
    __shared__ __nv_bfloat16 As_hi[128][40];
    __shared__ __nv_bfloat16 As_lo[128][40];
    __shared__ __nv_bfloat16 Bs_hi[128][40];
    __shared__ __nv_bfloat16 Bs_lo[128][40];

    const int mbase = blockIdx.x * 128;
    const int nbase = blockIdx.y * 128;
    const int tid  = threadIdx.x;
    const int lane = tid & 31;
    const int warp = tid >> 5;
    const int wy = warp >> 2;
    const int wx = warp & 3;
    const int g = lane >> 2;
    const int t = lane & 3;

    const int a_row  = lane & 15;
    const int a_csel = (lane >> 4) << 3;
    const int b_row  = (lane & 7) + ((lane >> 4) & 1) * 8;
    const int b_csel = ((lane >> 3) & 1) * 8;

    float acc[4][4][4];
#pragma unroll
    for (int mt = 0; mt < 4; mt++)
#pragma unroll
        for (int nt = 0; nt < 4; nt++)
#pragma unroll
            for (int e = 0; e < 4; e++) acc[mt][nt][e] = 0.f;

    for (int kt = 0; kt < HID; kt += 32) {
        const float* abase = g_attn + (size_t)(kt >> 7) * (S_LEN * HD) + (kt & 127);
        __syncthreads();
#pragma unroll
        for (int i = 0; i < 4; i++) {
            int j = tid + i * 256;
            int row = j >> 3, c4 = (j & 7) << 2;
            float4 v = *(const float4*)&abase[(size_t)(mbase + row) * HD + c4];
            float h0 = bf16rt(v.x), h1 = bf16rt(v.y), h2 = bf16rt(v.z), h3 = bf16rt(v.w);
            *(__nv_bfloat162*)&As_hi[row][c4]     = __floats2bfloat162_rn(h0, h1);
            *(__nv_bfloat162*)&As_hi[row][c4 + 2] = __floats2bfloat162_rn(h2, h3);
            *(__nv_bfloat162*)&As_lo[row][c4]     = __floats2bfloat162_rn(v.x - h0, v.y - h1);
            *(__nv_bfloat162*)&As_lo[row][c4 + 2] = __floats2bfloat162_rn(v.z - h2, v.w - h3);

            float4 w = *(const float4*)&ow[(size_t)(nbase + row) * HID + kt + c4];
            float g0 = bf16rt(w.x), g1 = bf16rt(w.y), g2 = bf16rt(w.z), g3 = bf16rt(w.w);
            *(__nv_bfloat162*)&Bs_hi[row][c4]     = __floats2bfloat162_rn(g0, g1);
            *(__nv_bfloat162*)&Bs_hi[row][c4 + 2] = __floats2bfloat162_rn(g2, g3);
            *(__nv_bfloat162*)&Bs_lo[row][c4]     = __floats2bfloat162_rn(w.x - g0, w.y - g1);
            *(__nv_bfloat162*)&Bs_lo[row][c4 + 2] = __floats2bfloat162_rn(w.z - g2, w.w - g3);
        }
        __syncthreads();

#pragma unroll
        for (int c3 = 0; c3 < 3; c3++) {
            const __nv_bfloat16 (*Asrc)[40] = (c3 == 2) ? As_lo : As_hi;
            const __nv_bfloat16 (*Bsrc)[40] = (c3 == 1) ? Bs_lo : Bs_hi;
#pragma unroll
            for (int k16 = 0; k16 < 2; k16++) {
                int k0 = k16 * 16;
                unsigned a[4][4];
#pragma unroll
                for (int mt = 0; mt < 4; mt++)
                    ldsm4(&Asrc[wy * 64 + mt * 16 + a_row][k0 + a_csel], a[mt]);
#pragma unroll
                for (int ntp = 0; ntp < 2; ntp++) {
                    unsigned bb[4];
                    ldsm4(&Bsrc[wx * 32 + ntp * 16 + b_row][k0 + b_csel], bb);
#pragma unroll
                    for (int mt = 0; mt < 4; mt++) {
                        mma_bf(acc[mt][2 * ntp],     a[mt], bb);
                        mma_bf(acc[mt][2 * ntp + 1], a[mt], bb + 2);
                    }
                }
            }
        }
    }

#pragma unroll
    for (int mt = 0; mt < 4; mt++) {
#pragma unroll
        for (int nt = 0; nt < 4; nt++) {
            int row = mbase + wy * 64 + mt * 16 + g;
            int col = wx * 32 + nt * 8 + 2 * t;
            float b0 = ob[nbase + col], b1 = ob[nbase + col + 1];
            float2 v0 = make_float2(acc[mt][nt][0] + b0, acc[mt][nt][1] + b1);
            float2 v1 = make_float2(acc[mt][nt][2] + b0, acc[mt][nt][3] + b1);
            *(float2*)&out[(size_t)row * HID + nbase + col]       = v0;
            *(float2*)&out[(size_t)(row + 8) * HID + nbase + col] = v1;
        }
    }
}

extern "C" void kernel_launch(void* const* d_in, const int* in_sizes, int n_in,
                              void* d_out, int out_size)
{
    const float* X  = (const float*)d_in[0];
    const float* qw = (const float*)d_in[1];
    const float* qb = (const float*)d_in[2];
    const float* kw = (const float*)d_in[3];
    const float* kb = (const float*)d_in[4];
    const float* vw = (const float*)d_in[5];
    const float* vb = (const float*)d_in[6];
    const float* ow = (const float*)d_in[7];
    const float* ob = (const float*)d_in[8];
    float* out = (float*)d_out;

    qkv_gemm_kernel<<<dim3(16, 16, 3), 256>>>(X, qw, qb, kw, kb, vw, vb);

    cudaFuncSetAttribute(attn_kernel,
                         cudaFuncAttributeMaxDynamicSharedMemorySize, ATT_SMEM);
    attn_kernel<<<dim3(16, 16), 256, ATT_SMEM>>>();

    out_gemm_kernel<<<dim3(16, 16), 256>>>(ow, ob, out);
}